// round 10
// baseline (speedup 1.0000x reference)
#include <cuda_runtime.h>
#include <cuda_bf16.h>
#include <cstdint>

// Problem shape (fixed by the dataset)
#define BB 64
#define CC 256
#define HH 80
#define WW 80
#define NN 100
#define IMG 640.0f

#define NPLANES (BB * CC)          // 16384 planes
#define PLANE_ELEMS (HH * WW)      // 6400 floats
#define PSTRIDE 84                 // padded smem row stride (floats); 84%4==0
#define PBUF (HH * PSTRIDE)        // 6720 floats per group buffer (26.88 KB)
#define NG 8                       // groups per CTA
#define GW 3                       // warps per group (96 threads)
#define GRID 152                   // persistent, one CTA per SM
#define TPB (NG * GW * 32)         // 768 threads
#define STRIDEP (GRID * NG)        // 1216 groups chip-wide
#define PF 10                      // rotating float4 prefetch depth (40 regs)
#define HALF 40                    // rows per loader half

__device__ __forceinline__ void named_bar(int id, int count) {
    asm volatile("bar.sync %0, %1;" :: "r"(id), "r"(count) : "memory");
}

// Strided row-span sum with 4 independent accumulators (no long FADD chain).
__device__ __forceinline__ float spanx(const float* __restrict__ Srow,
                                       int x1, int x2) {
    float s0 = 0.f, s1 = 0.f, s2 = 0.f, s3 = 0.f;
    int x = x1;
    for (; x + 4 <= x2; x += 4) {
        s0 += Srow[x];
        s1 += Srow[x + 1];
        s2 += Srow[x + 2];
        s3 += Srow[x + 3];
    }
    for (; x < x2; ++x) s0 += Srow[x];
    return (s0 + s1) + (s2 + s3);
}

__global__ __launch_bounds__(TPB, 1)
void roi_pool_kernel(const float* __restrict__ fmap,
                     const float* __restrict__ boxes,
                     float* __restrict__ out)
{
    extern __shared__ __align__(16) float P[];   // [NG][PBUF] = 215 KB

    const int tid  = threadIdx.x;
    const int wid  = tid >> 5;
    const int lane = tid & 31;
    const int bid  = blockIdx.x;

    const int g  = wid / GW;                 // group 0..7
    const int wg = wid % GW;                 // warp in group 0..2
    const int gt = wg * 32 + lane;           // 0..95 within group
    float* const S = P + (size_t)g * PBUF;

    const int G = bid * NG + g;              // global group id 0..1215

    for (int it = 0; ; ++it) {
        const int p = G + it * STRIDEP;
        if (p >= NPLANES) break;
        const float* plane = fmap + (size_t)p * PLANE_ELEMS;

        // ===== Pass 1: column cumsum (axis y) fused with LDG.128 loads. =====
        // Warps 0,1 / lanes 0..19: lane owns columns 4*lane..4*lane+3 over
        // rows [wg*40, wg*40+40). Bottom half stores PARTIAL sums
        // (compensated in the box pass). 16B loads x PF deep: 160B in
        // flight per lane -> 51 KB/SM total, DRAM stays saturated.
        if (wg < 2 && lane < 20) {
            const int y0 = wg * HALF;
            const float4* __restrict__ col =
                reinterpret_cast<const float4*>(plane) + lane;  // + 20 per row

            float4 buf[PF];
            #pragma unroll
            for (int d = 0; d < PF; ++d)
                buf[d] = __ldg(col + (y0 + d) * (WW / 4));

            float ax = 0.f, ay = 0.f, az = 0.f, aw = 0.f;
            #pragma unroll
            for (int k = 0; k < HALF; ++k) {
                float4 v = buf[k % PF];
                const int kn = k + PF;
                if (kn < HALF)
                    buf[k % PF] = __ldg(col + (y0 + kn) * (WW / 4));
                ax += v.x; ay += v.y; az += v.z; aw += v.w;
                float4 o = make_float4(ax, ay, az, aw);
                *reinterpret_cast<float4*>(S + (y0 + k) * PSTRIDE + 4 * lane) = o;
            }
        }
        named_bar(1 + g, GW * 32);

        // ===== Pass 2: boxes straight from column-cumsum rows. =====
        // True colsum diff over rows [y1,y2): stored[y2-1] - stored[y1-1]
        // + straddle * stored[39]  (bottom half holds partial sums).
        const int b = p / CC;
        const int c = p % CC;
        #pragma unroll
        for (int r0 = 0; r0 < 2; ++r0) {
            const int n = gt + r0 * 96;
            if (n < NN) {
                float4 bx = reinterpret_cast<const float4*>(boxes)[b * NN + n];
                // Reference math exactly: (coord/640)*80 in fp32 RN, int
                // truncation (non-negative => floor), clip into [0, dim].
                int x1 = (int)__fmul_rn(__fdiv_rn(bx.x, IMG), (float)WW);
                int y1 = (int)__fmul_rn(__fdiv_rn(bx.y, IMG), (float)HH);
                int x2 = (int)__fmul_rn(__fdiv_rn(bx.z, IMG), (float)WW);
                int y2 = (int)__fmul_rn(__fdiv_rn(bx.w, IMG), (float)HH);
                x1 = min(max(x1, 0), WW);
                y1 = min(max(y1, 0), HH);
                x2 = min(max(x2, 0), WW);
                y2 = min(max(y2, 0), HH);

                const int dy = y2 - y1;
                const int dx = x2 - x1;
                float r = 0.0f;
                if (dy > 0 && dx > 0) {
                    const int bot = y2 - 1;            // >= 0
                    const int top = y1 - 1;            // may be -1
                    float s = spanx(S + bot * PSTRIDE, x1, x2);
                    if (top >= 0)
                        s -= spanx(S + top * PSTRIDE, x1, x2);
                    // straddle coefficient: bottom-half partials miss rows
                    // [0,40); add stored row 39 (full top-half colsum) once
                    // iff bot is in the bottom half and top is not.
                    if (bot >= HALF && top < HALF)
                        s += spanx(S + (HALF - 1) * PSTRIDE, x1, x2);
                    r = __fdiv_rn(s, (float)(dy * dx));
                }
                out[((size_t)b * NN + n) * CC + c] = r;
            }
        }
        // All reads of S done before next iteration's pass 1 overwrites it.
        named_bar(1 + g, GW * 32);
    }
}

extern "C" void kernel_launch(void* const* d_in, const int* in_sizes, int n_in,
                              void* d_out, int out_size)
{
    const float* fmap  = (const float*)d_in[0];   // [64,256,80,80]
    const float* boxes = (const float*)d_in[1];   // [64,100,4]
    float* out = (float*)d_out;                   // [64,100,256]

    const int smem_bytes = NG * PBUF * sizeof(float);   // 215040
    cudaFuncSetAttribute(roi_pool_kernel,
                         cudaFuncAttributeMaxDynamicSharedMemorySize,
                         smem_bytes);

    roi_pool_kernel<<<GRID, TPB, smem_bytes>>>(fmap, boxes, out);
}

// round 11
// speedup vs baseline: 1.5929x; 1.5929x over previous
#include <cuda_runtime.h>
#include <cuda_bf16.h>
#include <cstdint>

// Problem shape (fixed by the dataset)
#define BB 64
#define CC 256
#define HH 80
#define WW 80
#define NN 100
#define IMG 640.0f

#define NPLANES (BB * CC)          // 16384 planes
#define PLANE_ELEMS (HH * WW)      // 6400 floats
#define PLANE_F4 (PLANE_ELEMS / 4) // 1600 16B chunks
#define PSTRIDE 84                 // padded smem row stride (floats)
#define PBUF (HH * PSTRIDE)        // 6720 floats per slot (26.88 KB)
#define NSLOTS 4                   // ring slots (2 per consumer group)
#define CW 3                       // consumer warps per group
#define GRID 304                   // persistent: two CTAs per SM
#define TPB 224                    // 6 consumer warps + 1 producer warp

__device__ __forceinline__ uint32_t smem_u32(const void* p) {
    uint32_t a;
    asm("{ .reg .u64 t; cvta.to.shared.u64 t, %1; cvt.u32.u64 %0, t; }"
        : "=r"(a) : "l"(p));
    return a;
}

__device__ __forceinline__ void cp_async16(uint32_t dst, const void* src) {
    asm volatile("cp.async.cg.shared.global [%0], [%1], 16;"
                 :: "r"(dst), "l"(src) : "memory");
}

__device__ __forceinline__ void mbar_init(uint32_t mbar, uint32_t count) {
    asm volatile("mbarrier.init.shared.b64 [%0], %1;"
                 :: "r"(mbar), "r"(count) : "memory");
}

__device__ __forceinline__ void mbar_arrive(uint32_t mbar) {
    asm volatile("mbarrier.arrive.shared.b64 _, [%0];" :: "r"(mbar) : "memory");
}

// Arrive once this thread's prior cp.asyncs complete (.noinc: counted in init).
__device__ __forceinline__ void cpasync_mbar_arrive(uint32_t mbar) {
    asm volatile("cp.async.mbarrier.arrive.noinc.shared::cta.b64 [%0];"
                 :: "r"(mbar) : "memory");
}

__device__ __forceinline__ void mbar_wait_parity(uint32_t mbar, uint32_t parity) {
    asm volatile(
        "{\n\t"
        ".reg .pred P1;\n\t"
        "WAIT_LOOP_%=:\n\t"
        "mbarrier.try_wait.parity.acquire.cta.shared::cta.b64 P1, [%0], %1, 0x989680;\n\t"
        "@P1 bra.uni WAIT_DONE_%=;\n\t"
        "bra.uni WAIT_LOOP_%=;\n\t"
        "WAIT_DONE_%=:\n\t"
        "}"
        :: "r"(mbar), "r"(parity) : "memory");
}

__device__ __forceinline__ void named_bar(int id, int count) {
    asm volatile("bar.sync %0, %1;" :: "r"(id), "r"(count) : "memory");
}

__global__ __launch_bounds__(TPB, 2)
void roi_pool_kernel(const float* __restrict__ fmap,
                     const float* __restrict__ boxes,
                     float* __restrict__ out)
{
    extern __shared__ __align__(16) float P[];   // [NSLOTS][PBUF] = 107.5 KB
    __shared__ __align__(8) uint64_t full_bar[NSLOTS];
    __shared__ __align__(8) uint64_t empty_bar[NSLOTS];

    const int tid  = threadIdx.x;
    const int wid  = tid >> 5;
    const int lane = tid & 31;
    const int bid  = blockIdx.x;
    const uint32_t pbase = smem_u32(P);

    if (tid == 0) {
        #pragma unroll
        for (int s = 0; s < NSLOTS; ++s) {
            mbar_init(smem_u32(&full_bar[s]), 32);  // 32 producer-lane arrivals
            mbar_init(smem_u32(&empty_bar[s]), 1);  // 1 consumer arrival
        }
        asm volatile("fence.proxy.async.shared::cta;" ::: "memory");
    }
    __syncthreads();

    if (wid == 6) {
        // ================= PRODUCER WARP =================
        // CTA's j-th plane: p = bid + j*GRID. Group j&1, slot 2*(j&1)+((j>>1)&1),
        // slot-fill counter u = j>>2.
        for (int j = 0; ; ++j) {
            const int p = bid + j * GRID;
            if (p >= NPLANES) break;
            const int slot = ((j & 1) << 1) + ((j >> 1) & 1);
            const int u = j >> 2;
            if (u > 0)
                mbar_wait_parity(smem_u32(&empty_bar[slot]), (u - 1) & 1);

            const float* plane = fmap + (size_t)p * PLANE_ELEMS;
            const uint32_t sbase = pbase + (uint32_t)(slot * PBUF) * 4u;
            // 1600 16B chunks, lane-interleaved (512B/warp-instr contiguous),
            // scattered into padded layout: chunk ch -> f4 slot (ch/20)*21+ch%20.
            #pragma unroll 5
            for (int k = 0; k < PLANE_F4 / 32; ++k) {
                const int ch  = lane + (k << 5);
                const int row = ch / 20;
                const int c4  = ch % 20;
                cp_async16(sbase + (uint32_t)(row * 21 + c4) * 16u,
                           plane + ch * 4);
            }
            cpasync_mbar_arrive(smem_u32(&full_bar[slot]));
        }
    } else {
        // ================= CONSUMER GROUPS (2 x 3 warps) =================
        const int g  = wid / CW;                // group 0..1
        const int gt = (wid % CW) * 32 + lane;  // 0..95 within group

        for (int k = 0; ; ++k) {
            const int j = (k << 1) + g;
            const int p = bid + j * GRID;
            if (p >= NPLANES) break;
            const int slot = (g << 1) + (k & 1);

            mbar_wait_parity(smem_u32(&full_bar[slot]), (k >> 1) & 1);
            float* S = P + slot * PBUF;

            // ---- Pass R: row prefix scan (axis x), float4, in place.
            // Row stride 21 float4 -> conflict-free phasing (proven R1/R4).
            if (gt < HH) {
                float4* row = reinterpret_cast<float4*>(S + gt * PSTRIDE);
                float acc = 0.0f;
                #pragma unroll
                for (int q = 0; q < WW / 4; ++q) {
                    float4 v4 = row[q];
                    v4.x += acc;
                    v4.y += v4.x;
                    v4.z += v4.y;
                    v4.w += v4.z;
                    acc = v4.w;
                    row[q] = v4;
                }
            }
            named_bar(1 + g, CW * 32);

            // ---- Pass B: 100 boxes; sum of row-span diffs over y.
            const int b = p / CC;
            const int c = p % CC;
            #pragma unroll
            for (int r0 = 0; r0 < 2; ++r0) {
                const int n = gt + r0 * 96;
                if (n < NN) {
                    float4 bx = reinterpret_cast<const float4*>(boxes)[b * NN + n];
                    // Reference math exactly: (coord/640)*80 fp32 RN, int
                    // truncation (non-negative => floor), clip to [0, dim].
                    int x1 = (int)__fmul_rn(__fdiv_rn(bx.x, IMG), (float)WW);
                    int y1 = (int)__fmul_rn(__fdiv_rn(bx.y, IMG), (float)HH);
                    int x2 = (int)__fmul_rn(__fdiv_rn(bx.z, IMG), (float)WW);
                    int y2 = (int)__fmul_rn(__fdiv_rn(bx.w, IMG), (float)HH);
                    x1 = min(max(x1, 0), WW);
                    y1 = min(max(y1, 0), HH);
                    x2 = min(max(x2, 0), WW);
                    y2 = min(max(y2, 0), HH);

                    const int dy = y2 - y1;
                    const int dx = x2 - x1;
                    float r = 0.0f;
                    if (dy > 0 && dx > 0) {
                        // row y contributes rowscan[y][x2-1] - rowscan[y][x1-1]
                        const float* colR = S + (x2 - 1);
                        float s;
                        if (x1 > 0) {
                            const float* colL = S + (x1 - 1);
                            float a0 = 0.f, a1 = 0.f, b0 = 0.f, b1 = 0.f;
                            int y = y1;
                            for (; y + 2 <= y2; y += 2) {
                                a0 += colR[y * PSTRIDE];
                                a1 += colR[(y + 1) * PSTRIDE];
                                b0 += colL[y * PSTRIDE];
                                b1 += colL[(y + 1) * PSTRIDE];
                            }
                            if (y < y2) { a0 += colR[y * PSTRIDE];
                                          b0 += colL[y * PSTRIDE]; }
                            s = (a0 + a1) - (b0 + b1);
                        } else {
                            float a0 = 0.f, a1 = 0.f, a2 = 0.f, a3 = 0.f;
                            int y = y1;
                            for (; y + 4 <= y2; y += 4) {
                                a0 += colR[y * PSTRIDE];
                                a1 += colR[(y + 1) * PSTRIDE];
                                a2 += colR[(y + 2) * PSTRIDE];
                                a3 += colR[(y + 3) * PSTRIDE];
                            }
                            for (; y < y2; ++y) a0 += colR[y * PSTRIDE];
                            s = (a0 + a1) + (a2 + a3);
                        }
                        r = __fdiv_rn(s, (float)(dy * dx));
                    }
                    out[((size_t)b * NN + n) * CC + c] = r;
                }
            }
            named_bar(1 + g, CW * 32);   // all reads of S complete
            if (gt == 0)
                mbar_arrive(smem_u32(&empty_bar[slot]));
        }
    }
}

extern "C" void kernel_launch(void* const* d_in, const int* in_sizes, int n_in,
                              void* d_out, int out_size)
{
    const float* fmap  = (const float*)d_in[0];   // [64,256,80,80]
    const float* boxes = (const float*)d_in[1];   // [64,100,4]
    float* out = (float*)d_out;                   // [64,100,256]

    const int smem_bytes = NSLOTS * PBUF * sizeof(float);   // 107520
    cudaFuncSetAttribute(roi_pool_kernel,
                         cudaFuncAttributeMaxDynamicSharedMemorySize,
                         smem_bytes);

    roi_pool_kernel<<<GRID, TPB, smem_bytes>>>(fmap, boxes, out);
}